// round 8
// baseline (speedup 1.0000x reference)
#include <cuda_runtime.h>
#include <cuda_bf16.h>
#include <cstdint>
#define DI __device__ __forceinline__

constexpr int Bn=16, Sn=1024, W=768;
__device__ __align__(128) unsigned short g_A[Bn*Sn*W];
__device__ __align__(128) unsigned short g_B[Bn*Sn*W];

DI unsigned short f2bf(float x){ __nv_bfloat16 h=__float2bfloat16(x); return *(unsigned short*)&h; }

// kernel 1: amplitudes. Row: [c(256)|s(256)|d(256)], d = c-s (A side) or c+s (B side)
__global__ void iqp_amp_kernel(const float* __restrict__ Q, const float* __restrict__ K){
  const int isK=blockIdx.y;
  const float* X = isK?K:Q;
  const int t0 = blockIdx.x*16;
  __shared__ float xs[16][8];
  const int tid=threadIdx.x;
  if(tid<128) xs[tid>>3][tid&7]=X[t0*8+tid];
  __syncthreads();
  const int z=tid;
  unsigned short* G = isK? g_B : g_A;
#pragma unroll 4
  for(int t=0;t<16;++t){
    float sq=0.f,L=0.f;
#pragma unroll
    for(int i=0;i<8;++i){ float xi=xs[t][i]; sq+=xi*xi; L+=((z>>i)&1)?-xi:xi; }
    float ph=-0.5f*L-0.25f*(L*L-sq), s,c; __sincosf(ph,&s,&c);
    size_t base=(size_t)(t0+t)*W;
    G[base+z]=f2bf(c); G[base+256+z]=f2bf(s);
    G[base+512+z]=f2bf(isK? c+s : c-s);
  }
}

// kernel 2: fused fid-attention. i-tile 64, K=128 chunks, 2-stage ring, V from global.
constexpr int STG=49152;       // A[64x128]=16384 + B[128x128]=32768
constexpr int SM_RING=0;       // 2 stages = 98304
constexpr int SM_CS=98304;     // [32][8] f32 = 1024
constexpr int SM_SV=99328;     // [8] f32
constexpr int SM_RED=0;        // reuse ring after loop
constexpr int SM_TOTAL=99360;

DI uint32_t swz(int r,int c){ return (uint32_t)(r*128 + ((c^(r&7))<<4)); }
DI void cp16(uint32_t d,const void* s){ asm volatile("cp.async.cg.shared.global [%0],[%1],16;\n"::"r"(d),"l"(s):"memory"); }
DI void cpc(){ asm volatile("cp.async.commit_group;\n":::"memory"); }
DI void ldsm_x4(uint32_t* r,uint32_t a){
  asm volatile("ldmatrix.sync.aligned.m8n8.x4.shared.b16 {%0,%1,%2,%3},[%4];\n"
    :"=r"(r[0]),"=r"(r[1]),"=r"(r[2]),"=r"(r[3]):"r"(a));
}
DI void mma16816(float* c,const uint32_t* a,uint32_t b0,uint32_t b1){
  asm volatile("mma.sync.aligned.m16n8k16.row.col.f32.bf16.bf16.f32 {%0,%1,%2,%3},{%4,%5,%6,%7},{%8,%9},{%0,%1,%2,%3};\n"
    :"+f"(c[0]),"+f"(c[1]),"+f"(c[2]),"+f"(c[3])
    :"r"(a[0]),"r"(a[1]),"r"(a[2]),"r"(a[3]),"r"(b0),"r"(b1));
}
DI uint32_t pack2(float lo,float hi){ uint32_t r; asm("cvt.rn.bf16x2.f32 %0,%1,%2;\n":"=r"(r):"f"(hi),"f"(lo)); return r; }

__global__ __launch_bounds__(256,2)
void qattn_kernel(const float* __restrict__ V, float* __restrict__ Out){
  extern __shared__ char smem[];
  const uint32_t sb=(uint32_t)__cvta_generic_to_shared(smem);
  const int b=blockIdx.y, it=blockIdx.x, tid=threadIdx.x;
  const int lane=tid&31, warp=tid>>5;
  const int wm=warp>>2, wn=warp&3;   // 2M x 4N warps, 32x32 tiles over [64 x 128]

  const unsigned short* gAi = g_A + (size_t)(b*Sn+it*64)*W;
  const unsigned short* gBb = g_B + (size_t)b*Sn*W;

  auto loadChunk=[&](int step){
    int jt=step/6, kc=step%6;
    uint32_t base=sb+SM_RING+(uint32_t)((step&1)*STG);
    const unsigned short* sA = gAi + kc*128;
#pragma unroll
    for(int s2=0;s2<2;++s2){
      const unsigned short* src=sA+s2*64;
      uint32_t dst=base+s2*8192;
#pragma unroll
      for(int m=0;m<2;++m){ int ch=tid+m*256, r=ch>>3, cx=ch&7;
        cp16(dst+swz(r,cx), src+(size_t)r*W+cx*8); }
    }
    const unsigned short* sB = gBb + (size_t)jt*128*W + kc*128;
#pragma unroll
    for(int s2=0;s2<2;++s2){
      const unsigned short* src=sB+s2*64;
      uint32_t dst=base+16384+s2*16384;
#pragma unroll
      for(int m=0;m<4;++m){ int ch=tid+m*256, r=ch>>3, cx=ch&7;
        cp16(dst+swz(r,cx), src+(size_t)r*W+cx*8); }
    }
    cpc();
  };
  loadChunk(0);

  // colsum(V) from global
  const float* gV = V + (size_t)b*Sn*8;
  {
    int e=tid&7, jg=tid>>3; float part=0.f;
#pragma unroll
    for(int k=0;k<32;++k) part+=gV[(jg+k*32)*8+e];
    *(float*)(smem+SM_CS+(jg*8+e)*4)=part;
  }
  __syncthreads();
  if(tid<8){ float s=0.f; for(int g=0;g<32;++g) s+=*(float*)(smem+SM_CS+(g*8+tid)*4);
             *(float*)(smem+SM_SV+tid*4)=s; }

  float accX[2][4][4], accY[2][4][4], accO[2][4];
#pragma unroll
  for(int m=0;m<2;++m)
#pragma unroll
    for(int n=0;n<4;++n)
#pragma unroll
      for(int x=0;x<4;++x){ accX[m][n][x]=0.f; accY[m][n][x]=0.f; accO[m][x]=0.f; }

  const int lr=lane&15, lch=lane>>4;
  const int brow=(lane&7)+((lane>>4)<<3), bco=(lane>>3)&1;
  const int ve=lane>>2, vj=2*(lane&3);
  const float sc=2.0f/65536.0f;

  for(int step=0;step<48;++step){
    const int kc=step%6, jt=step/6;
    asm volatile("cp.async.wait_group 0;\n":::"memory");
    __syncthreads();
    if(step+1<48) loadChunk(step+1);          // other stage, safe post-sync
    const uint32_t base=sb+SM_RING+(uint32_t)((step&1)*STG);
    float (&acc)[2][4][4] = (kc<2)? accX : accY;   // m1->X; m2,m3->Y

#pragma unroll
    for(int k16=0;k16<8;++k16){
      const int s2=k16>>2, kk=k16&3;
      const uint32_t at=base+s2*8192, bt=base+16384+s2*16384;
      uint32_t aF[2][4], bF[2][4];
      ldsm_x4(aF[0], at+swz(wm*32+lr,    kk*2+lch));
      ldsm_x4(aF[1], at+swz(wm*32+16+lr, kk*2+lch));
      ldsm_x4(bF[0], bt+swz(wn*32+brow,    kk*2+bco));
      ldsm_x4(bF[1], bt+swz(wn*32+16+brow, kk*2+bco));
#pragma unroll
      for(int m=0;m<2;++m)
#pragma unroll
        for(int nf=0;nf<4;++nf)
          mma16816(acc[m][nf], aF[m], bF[nf>>1][(nf&1)*2], bF[nf>>1][(nf&1)*2+1]);
    }

    if(kc==3){   // butterfly: X=m1+m2=re, Y=m2-m1 (m3 adds on top -> im)
#pragma unroll
      for(int m=0;m<2;++m)
#pragma unroll
        for(int n=0;n<4;++n)
#pragma unroll
          for(int x=0;x<4;++x){
            float a=accX[m][n][x], y=accY[m][n][x];
            accX[m][n][x]=a+y; accY[m][n][x]=y-a;
          }
    }

    if(kc==5){   // P = 2*fid -> bf16 A-frags -> P@V (V frags straight from global)
      uint32_t vf[2][2];
#pragma unroll
      for(int q=0;q<2;++q){
        int j0=jt*128+wn*32+q*16+vj;
        float v0=gV[j0*8+ve],     v1=gV[(j0+1)*8+ve];
        float v2=gV[(j0+8)*8+ve], v3=gV[(j0+9)*8+ve];
        vf[q][0]=pack2(v0,v1); vf[q][1]=pack2(v2,v3);
      }
#pragma unroll
      for(int m=0;m<2;++m)
#pragma unroll
        for(int q=0;q<2;++q){
          const int n0=2*q, n1=2*q+1;
          float p[8];
#pragma unroll
          for(int x=0;x<4;++x){
            p[x]  =(accX[m][n0][x]*accX[m][n0][x]+accY[m][n0][x]*accY[m][n0][x])*sc;
            p[4+x]=(accX[m][n1][x]*accX[m][n1][x]+accY[m][n1][x]*accY[m][n1][x])*sc;
          }
          uint32_t pa[4]={pack2(p[0],p[1]),pack2(p[2],p[3]),pack2(p[4],p[5]),pack2(p[6],p[7])};
          mma16816(accO[m], pa, vf[q][0], vf[q][1]);
        }
#pragma unroll
      for(int m=0;m<2;++m)
#pragma unroll
        for(int n=0;n<4;++n)
#pragma unroll
          for(int x=0;x<4;++x){ accX[m][n][x]=0.f; accY[m][n][x]=0.f; }
    }
  }

  __syncthreads();
  // reduce 4 warpN partials, subtract colsum(V), store (64 rows x 8)
  {
    float* red=(float*)(smem+SM_RED)+wn*512;
    const int g=lane>>2, e0=(lane&3)*2;
#pragma unroll
    for(int m=0;m<2;++m){
      int r0=wm*32+m*16+g;
      red[r0*8+e0]=accO[m][0];     red[r0*8+e0+1]=accO[m][1];
      red[(r0+8)*8+e0]=accO[m][2]; red[(r0+8)*8+e0+1]=accO[m][3];
    }
  }
  __syncthreads();
  const float* redall=(const float*)(smem+SM_RED);
  size_t ob=(size_t)(b*Sn+it*64)*8;
#pragma unroll
  for(int rep=0;rep<2;++rep){
    int idx=tid+rep*256, e=idx&7;
    float v=redall[idx]+redall[512+idx]+redall[1024+idx]+redall[1536+idx]
           -*(const float*)(smem+SM_SV+e*4);
    Out[ob+idx]=v;
  }
}

extern "C" void kernel_launch(void* const* d_in,const int* in_sizes,int n_in,void* d_out,int out_size){
  (void)in_sizes;(void)n_in;(void)out_size;
  const float* Q=(const float*)d_in[0];
  const float* K=(const float*)d_in[1];
  const float* V=(const float*)d_in[2];
  float* Out=(float*)d_out;
  dim3 g1(Bn*Sn/16,2);
  iqp_amp_kernel<<<g1,256>>>(Q,K);
  cudaFuncSetAttribute(qattn_kernel,cudaFuncAttributeMaxDynamicSharedMemorySize,SM_TOTAL);
  dim3 g2(16,Bn);
  qattn_kernel<<<g2,256,SM_TOTAL>>>(V,Out);
}

// round 9
// speedup vs baseline: 1.9425x; 1.9425x over previous
#include <cuda_runtime.h>
#include <cuda_bf16.h>
#include <cstdint>
#define DI __device__ __forceinline__

constexpr int Bn=16, Sn=1024, W=768;
__device__ __align__(128) unsigned short g_A[Bn*Sn*W];
__device__ __align__(128) unsigned short g_B[Bn*Sn*W];

DI unsigned short f2bf(float x){ __nv_bfloat16 h=__float2bfloat16(x); return *(unsigned short*)&h; }

// kernel 1: amplitudes. Row: [c(256)|s(256)|d(256)], d = c-s (A side) or c+s (B side)
__global__ void iqp_amp_kernel(const float* __restrict__ Q, const float* __restrict__ K){
  const int isK=blockIdx.y;
  const float* X = isK?K:Q;
  const int t0 = blockIdx.x*16;
  __shared__ float xs[16][8];
  const int tid=threadIdx.x;
  if(tid<128) xs[tid>>3][tid&7]=X[t0*8+tid];
  __syncthreads();
  const int z=tid;
  unsigned short* G = isK? g_B : g_A;
#pragma unroll 4
  for(int t=0;t<16;++t){
    float sq=0.f,L=0.f;
#pragma unroll
    for(int i=0;i<8;++i){ float xi=xs[t][i]; sq+=xi*xi; L+=((z>>i)&1)?-xi:xi; }
    float ph=-0.5f*L-0.25f*(L*L-sq), s,c; __sincosf(ph,&s,&c);
    size_t base=(size_t)(t0+t)*W;
    G[base+z]=f2bf(c); G[base+256+z]=f2bf(s);
    G[base+512+z]=f2bf(isK? c+s : c-s);
  }
}

// kernel 2: fused fid-attention. i-tile 64, K=128 chunks, 2-stage ring, V from global.
constexpr int STG=49152;       // A[64x128]=16384 + B[128x128]=32768
constexpr int SM_RING=0;       // 2 stages = 98304
constexpr int SM_CS=98304;     // [32][8] f32
constexpr int SM_SV=99328;     // [8] f32
constexpr int SM_RED=0;        // reuse ring after loop
constexpr int SM_TOTAL=99360;

DI uint32_t swz(int r,int c){ return (uint32_t)(r*128 + ((c^(r&7))<<4)); }
DI void cp16(uint32_t d,const void* s){ asm volatile("cp.async.cg.shared.global [%0],[%1],16;\n"::"r"(d),"l"(s):"memory"); }
DI void cpc(){ asm volatile("cp.async.commit_group;\n":::"memory"); }
DI void ldsm_x4(uint32_t* r,uint32_t a){
  asm volatile("ldmatrix.sync.aligned.m8n8.x4.shared.b16 {%0,%1,%2,%3},[%4];\n"
    :"=r"(r[0]),"=r"(r[1]),"=r"(r[2]),"=r"(r[3]):"r"(a));
}
DI void mma16816(float* c,const uint32_t* a,uint32_t b0,uint32_t b1){
  asm volatile("mma.sync.aligned.m16n8k16.row.col.f32.bf16.bf16.f32 {%0,%1,%2,%3},{%4,%5,%6,%7},{%8,%9},{%0,%1,%2,%3};\n"
    :"+f"(c[0]),"+f"(c[1]),"+f"(c[2]),"+f"(c[3])
    :"r"(a[0]),"r"(a[1]),"r"(a[2]),"r"(a[3]),"r"(b0),"r"(b1));
}
DI uint32_t pack2(float lo,float hi){ uint32_t r; asm("cvt.rn.bf16x2.f32 %0,%1,%2;\n":"=r"(r):"f"(hi),"f"(lo)); return r; }

__global__ __launch_bounds__(256,2)
void qattn_kernel(const float* __restrict__ V, float* __restrict__ Out){
  extern __shared__ char smem[];
  const uint32_t sb=(uint32_t)__cvta_generic_to_shared(smem);
  const int b=blockIdx.y, it=blockIdx.x, tid=threadIdx.x;
  const int lane=tid&31, warp=tid>>5;
  const int wm=warp>>2, wn=warp&3;   // 2M x 4N warps, 32x32 tiles over [64 x 128]

  const unsigned short* gAi = g_A + (size_t)(b*Sn+it*64)*W;
  const unsigned short* gBb = g_B + (size_t)b*Sn*W;

  auto loadChunk=[&](int jt,int kc,int st){
    uint32_t base=sb+SM_RING+(uint32_t)(st*STG);
    const unsigned short* sA = gAi + kc*128;
#pragma unroll
    for(int s2=0;s2<2;++s2){
      const unsigned short* src=sA+s2*64;
      uint32_t dst=base+s2*8192;
#pragma unroll
      for(int m=0;m<2;++m){ int ch=tid+m*256, r=ch>>3, cx=ch&7;
        cp16(dst+swz(r,cx), src+(size_t)r*W+cx*8); }
    }
    const unsigned short* sB = gBb + (size_t)jt*128*W + kc*128;
#pragma unroll
    for(int s2=0;s2<2;++s2){
      const unsigned short* src=sB+s2*64;
      uint32_t dst=base+16384+s2*16384;
#pragma unroll
      for(int m=0;m<4;++m){ int ch=tid+m*256, r=ch>>3, cx=ch&7;
        cp16(dst+swz(r,cx), src+(size_t)r*W+cx*8); }
    }
    cpc();
  };
  loadChunk(0,0,0);

  // colsum(V) from global
  const float* gV = V + (size_t)b*Sn*8;
  {
    int e=tid&7, jg=tid>>3; float part=0.f;
#pragma unroll
    for(int k=0;k<32;++k) part+=gV[(jg+k*32)*8+e];
    *(float*)(smem+SM_CS+(jg*8+e)*4)=part;
  }
  __syncthreads();
  if(tid<8){ float s=0.f; for(int g=0;g<32;++g) s+=*(float*)(smem+SM_CS+(g*8+tid)*4);
             *(float*)(smem+SM_SV+tid*4)=s; }

  float accX[2][4][4], accY[2][4][4], accO[2][4];
#pragma unroll
  for(int m=0;m<2;++m)
#pragma unroll
    for(int n=0;n<4;++n)
#pragma unroll
      for(int x=0;x<4;++x){ accX[m][n][x]=0.f; accY[m][n][x]=0.f; accO[m][x]=0.f; }

  const int lr=lane&15, lch=lane>>4;
  const int brow=(lane&7)+((lane>>4)<<3), bco=(lane>>3)&1;
  const int ve=lane>>2, vj=2*(lane&3);
  const float sc=2.0f/65536.0f;

  for(int jt=0;jt<8;++jt){
#pragma unroll
    for(int kc=0;kc<6;++kc){          // kc compile-time -> static acc selection
      asm volatile("cp.async.wait_group 0;\n":::"memory");
      __syncthreads();
      if(jt<7||kc<5){                  // prefetch next chunk into other stage
        int nj=(kc==5)?jt+1:jt, nk=(kc==5)?0:kc+1;
        loadChunk(nj,nk,(kc+1)&1);
      }
      const uint32_t base=sb+SM_RING+(uint32_t)((kc&1)*STG);
      float (&acc)[2][4][4] = (kc<2)? accX : accY;   // m1->X; m2,m3->Y

#pragma unroll
      for(int k16=0;k16<8;++k16){
        const int s2=k16>>2, kk=k16&3;
        const uint32_t at=base+s2*8192, bt=base+16384+s2*16384;
        uint32_t aF[2][4], bF[2][4];
        ldsm_x4(aF[0], at+swz(wm*32+lr,    kk*2+lch));
        ldsm_x4(aF[1], at+swz(wm*32+16+lr, kk*2+lch));
        ldsm_x4(bF[0], bt+swz(wn*32+brow,    kk*2+bco));
        ldsm_x4(bF[1], bt+swz(wn*32+16+brow, kk*2+bco));
#pragma unroll
        for(int m=0;m<2;++m)
#pragma unroll
          for(int nf=0;nf<4;++nf)
            mma16816(acc[m][nf], aF[m], bF[nf>>1][(nf&1)*2], bF[nf>>1][(nf&1)*2+1]);
      }

      if(kc==3){   // butterfly: X=m1+m2=re, Y=m2-m1 (m3 adds on top -> im)
#pragma unroll
        for(int m=0;m<2;++m)
#pragma unroll
          for(int n=0;n<4;++n)
#pragma unroll
            for(int x=0;x<4;++x){
              float a=accX[m][n][x], y=accY[m][n][x];
              accX[m][n][x]=a+y; accY[m][n][x]=y-a;
            }
      }

      if(kc==5){   // P = 2*fid -> bf16 A-frags -> P@V (V frags from global/L2)
        uint32_t vf[2][2];
#pragma unroll
        for(int q=0;q<2;++q){
          int j0=jt*128+wn*32+q*16+vj;
          float v0=gV[j0*8+ve],     v1=gV[(j0+1)*8+ve];
          float v2=gV[(j0+8)*8+ve], v3=gV[(j0+9)*8+ve];
          vf[q][0]=pack2(v0,v1); vf[q][1]=pack2(v2,v3);
        }
#pragma unroll
        for(int m=0;m<2;++m)
#pragma unroll
          for(int q=0;q<2;++q){
            const int n0=2*q, n1=2*q+1;
            float p[8];
#pragma unroll
            for(int x=0;x<4;++x){
              p[x]  =(accX[m][n0][x]*accX[m][n0][x]+accY[m][n0][x]*accY[m][n0][x])*sc;
              p[4+x]=(accX[m][n1][x]*accX[m][n1][x]+accY[m][n1][x]*accY[m][n1][x])*sc;
            }
            uint32_t pa[4]={pack2(p[0],p[1]),pack2(p[2],p[3]),pack2(p[4],p[5]),pack2(p[6],p[7])};
            mma16816(accO[m], pa, vf[q][0], vf[q][1]);
          }
#pragma unroll
        for(int m=0;m<2;++m)
#pragma unroll
          for(int n=0;n<4;++n)
#pragma unroll
            for(int x=0;x<4;++x){ accX[m][n][x]=0.f; accY[m][n][x]=0.f; }
      }
    }
  }

  __syncthreads();
  // reduce 4 warpN partials, subtract colsum(V), store (64 rows x 8)
  {
    float* red=(float*)(smem+SM_RED)+wn*512;
    const int g=lane>>2, e0=(lane&3)*2;
#pragma unroll
    for(int m=0;m<2;++m){
      int r0=wm*32+m*16+g;
      red[r0*8+e0]=accO[m][0];     red[r0*8+e0+1]=accO[m][1];
      red[(r0+8)*8+e0]=accO[m][2]; red[(r0+8)*8+e0+1]=accO[m][3];
    }
  }
  __syncthreads();
  const float* redall=(const float*)(smem+SM_RED);
  size_t ob=(size_t)(b*Sn+it*64)*8;
#pragma unroll
  for(int rep=0;rep<2;++rep){
    int idx=tid+rep*256, e=idx&7;
    float v=redall[idx]+redall[512+idx]+redall[1024+idx]+redall[1536+idx]
           -*(const float*)(smem+SM_SV+e*4);
    Out[ob+idx]=v;
  }
}

extern "C" void kernel_launch(void* const* d_in,const int* in_sizes,int n_in,void* d_out,int out_size){
  (void)in_sizes;(void)n_in;(void)out_size;
  const float* Q=(const float*)d_in[0];
  const float* K=(const float*)d_in[1];
  const float* V=(const float*)d_in[2];
  float* Out=(float*)d_out;
  dim3 g1(Bn*Sn/16,2);
  iqp_amp_kernel<<<g1,256>>>(Q,K);
  cudaFuncSetAttribute(qattn_kernel,cudaFuncAttributeMaxDynamicSharedMemorySize,SM_TOTAL);
  dim3 g2(16,Bn);
  qattn_kernel<<<g2,256,SM_TOTAL>>>(V,Out);
}